// round 3
// baseline (speedup 1.0000x reference)
#include <cuda_runtime.h>

// Problem shapes (fixed)
#define BB 32
#define PP 256
#define NN 1024
#define EE 512
#define HH 16
#define DD 32

typedef unsigned long long ull;

// Scratch (device globals: allocation-free per harness rules)
__device__ float g_q  [BB*PP*EE];   // q = q_first + enc@Wq^T, layout [B,P,(h,d)]
__device__ float g_att[BB*PP*EE];   // attention out, layout [B,P,(h,d)]
__device__ float g_mh [BB*PP*EE];   // combined heads [B,P,E]
__device__ float g_s2 [BB*PP*NN];   // exp(pointer logits) [B,P,N]

// ---- packed f32x2 helpers (sm_103a FFMA2 path) -----------------------------
__device__ __forceinline__ ull fma2(ull a, ull b, ull c) {
    ull d;
    asm("fma.rn.f32x2 %0, %1, %2, %3;" : "=l"(d) : "l"(a), "l"(b), "l"(c));
    return d;
}
__device__ __forceinline__ ull mul2(ull a, ull b) {
    ull d;
    asm("mul.rn.f32x2 %0, %1, %2;" : "=l"(d) : "l"(a), "l"(b));
    return d;
}
__device__ __forceinline__ ull pk2(float lo, float hi) {
    ull r;
    asm("mov.b64 %0, {%1, %2};" : "=l"(r) : "f"(lo), "f"(hi));
    return r;
}
__device__ __forceinline__ float hadd2(ull v) {
    float lo, hi;
    asm("mov.b64 {%0, %1}, %2;" : "=f"(lo), "=f"(hi) : "l"(v));
    return lo + hi;
}

// ---------------------------------------------------------------------------
// GEMM C[M,512] = A[M,512] @ W[512,512]^T   (C[m,n] = sum_k A[m,k] W[n,k])
// MODE 0: A=enc, epilogue adds q_first ([B,H,P,D]) -> g_q
// MODE 1: A=g_att -> g_mh
// Tile 128(m) x 64(n), K-chunk 16, 256 threads, micro 8x4, f32x2 over K.
// Double-buffered smem: one __syncthreads per chunk, LDG overlapped w/ compute.
// ---------------------------------------------------------------------------
#define LDA 20
template <int MODE>
__global__ void __launch_bounds__(256) gemm_aw_kernel(
    const float* __restrict__ Ain,
    const float* __restrict__ W,
    const float* __restrict__ qfirst)
{
    const float* A = (MODE == 0) ? Ain : g_att;
    float*       C = (MODE == 0) ? g_q : g_mh;

    __shared__ float As[2][128 * LDA];   // [m][k], k contiguous
    __shared__ float Ws[2][64 * LDA];    // [n][k]

    const int tx = threadIdx.x;       // 0..15 -> n
    const int ty = threadIdx.y;       // 0..15 -> m
    const int t  = ty * 16 + tx;
    const int m0 = blockIdx.y * 128;
    const int n0 = blockIdx.x * 64;

    const int ar = t >> 2;            // 0..63 (row, two passes for A)
    const int ac = (t & 3) * 4;       // k col 0,4,8,12

    const float* pA0 = A + (m0 + ar) * EE + ac;
    const float* pA1 = A + (m0 + 64 + ar) * EE + ac;
    const float* pW  = W + (n0 + ar) * EE + ac;

    ull acc2[8][4];
#pragma unroll
    for (int i = 0; i < 8; i++)
#pragma unroll
        for (int j = 0; j < 4; j++) acc2[i][j] = 0ull;

    // prologue: chunk 0 -> buffer 0
    float4 a0 = *(const float4*)(pA0);
    float4 a1 = *(const float4*)(pA1);
    float4 wv = *(const float4*)(pW);
    *(float4*)(&As[0][ar * LDA + ac])        = a0;
    *(float4*)(&As[0][(64 + ar) * LDA + ac]) = a1;
    *(float4*)(&Ws[0][ar * LDA + ac])        = wv;
    __syncthreads();

#pragma unroll 1
    for (int c = 0; c < 32; c++) {
        const int cur = c & 1;
        if (c < 31) {
            const int k1 = (c + 1) * 16;
            a0 = *(const float4*)(pA0 + k1);
            a1 = *(const float4*)(pA1 + k1);
            wv = *(const float4*)(pW + k1);
        }
#pragma unroll
        for (int kp = 0; kp < 8; kp++) {
            ull a2[8], b2[4];
#pragma unroll
            for (int i = 0; i < 8; i++)
                a2[i] = *(const ull*)(&As[cur][(ty * 8 + i) * LDA + 2 * kp]);
#pragma unroll
            for (int j = 0; j < 4; j++)
                b2[j] = *(const ull*)(&Ws[cur][(tx * 4 + j) * LDA + 2 * kp]);
#pragma unroll
            for (int i = 0; i < 8; i++)
#pragma unroll
                for (int j = 0; j < 4; j++)
                    acc2[i][j] = fma2(a2[i], b2[j], acc2[i][j]);
        }
        if (c < 31) {
            const int nxt = cur ^ 1;
            *(float4*)(&As[nxt][ar * LDA + ac])        = a0;
            *(float4*)(&As[nxt][(64 + ar) * LDA + ac]) = a1;
            *(float4*)(&Ws[nxt][ar * LDA + ac])        = wv;
            __syncthreads();
        }
    }

#pragma unroll
    for (int i = 0; i < 8; i++) {
        const int m = m0 + ty * 8 + i;        // m = b*256 + p
#pragma unroll
        for (int j = 0; j < 4; j++) {
            const int n = n0 + tx * 4 + j;    // n = h*32 + d
            float val = hadd2(acc2[i][j]);
            if (MODE == 0) {
                const int b = m >> 8, p = m & 255;
                const int h = n >> 5, d = n & 31;
                val += qfirst[((b * HH + h) * PP + p) * DD + d];
            }
            C[m * EE + n] = val;
        }
    }
}

// ---------------------------------------------------------------------------
// Masked attention per (b,h). 128 threads; thread owns queries p and p+128.
// f32x2 over D; QK uses 4 independent accumulation chains to saturate the
// fma pipe. One-pass exp softmax (scores bounded; masked -> exact 0).
// ---------------------------------------------------------------------------
__global__ void __launch_bounds__(128) attn_kernel(
    const float* __restrict__ kmat,
    const float* __restrict__ vmat,
    const float* __restrict__ mask)
{
    const int bh = blockIdx.x;
    const int b = bh >> 4, h = bh & 15;
    const int t = threadIdx.x;        // 0..127
    const int p0 = t, p1 = t + 128;

    __shared__ float ks[128 * 32];
    __shared__ float vs[128 * 32];

    ull q2[2][16];
    {
        const ull* qp0 = (const ull*)(g_q + (b * PP + p0) * EE + h * DD);
        const ull* qp1 = (const ull*)(g_q + (b * PP + p1) * EE + h * DD);
#pragma unroll
        for (int i = 0; i < 16; i++) { q2[0][i] = qp0[i]; q2[1][i] = qp1[i]; }
    }

    ull acc2[2][16];
#pragma unroll
    for (int q = 0; q < 2; q++)
#pragma unroll
        for (int i = 0; i < 16; i++) acc2[q][i] = 0ull;
    float l0 = 0.f, l1 = 0.f;

    const float* mrow0 = mask + (b * PP + p0) * NN;
    const float* mrow1 = mask + (b * PP + p1) * NN;
    const float scale = 0.17677669529663687f;  // 1/sqrt(32)

    for (int n0 = 0; n0 < NN; n0 += 128) {
        const long base = ((long)(b * HH + h) * NN + n0) * DD;
        const float4* kg = (const float4*)(kmat + base);
        const float4* vg = (const float4*)(vmat + base);
        __syncthreads();
#pragma unroll
        for (int i = 0; i < 8; i++) {
            const int idx = i * 128 + t;    // 1024 float4 per tile
            ((float4*)ks)[idx] = kg[idx];
            ((float4*)vs)[idx] = vg[idx];
        }
        __syncthreads();

#pragma unroll 2
        for (int n = 0; n < 128; n++) {
            const ull* kr = (const ull*)(ks + n * 32);   // broadcast reads
            ull s0a = 0ull, s0b = 0ull, s1a = 0ull, s1b = 0ull;
#pragma unroll
            for (int i = 0; i < 8; i++) {
                const ull kv0 = kr[2 * i];
                const ull kv1 = kr[2 * i + 1];
                s0a = fma2(q2[0][2 * i],     kv0, s0a);
                s0b = fma2(q2[0][2 * i + 1], kv1, s0b);
                s1a = fma2(q2[1][2 * i],     kv0, s1a);
                s1b = fma2(q2[1][2 * i + 1], kv1, s1b);
            }
            const float e0 = __expf((hadd2(s0a) + hadd2(s0b)) * scale + mrow0[n0 + n]);
            const float e1 = __expf((hadd2(s1a) + hadd2(s1b)) * scale + mrow1[n0 + n]);
            l0 += e0; l1 += e1;
            const ull e0d = pk2(e0, e0);
            const ull e1d = pk2(e1, e1);
            const ull* vr = (const ull*)(vs + n * 32);
#pragma unroll
            for (int i = 0; i < 16; i++) {
                const ull vv = vr[i];
                acc2[0][i] = fma2(e0d, vv, acc2[0][i]);
                acc2[1][i] = fma2(e1d, vv, acc2[1][i]);
            }
        }
    }

    const ull inv0 = pk2(1.f / l0, 1.f / l0);
    const ull inv1 = pk2(1.f / l1, 1.f / l1);
    ull* op0 = (ull*)(g_att + (b * PP + p0) * EE + h * DD);
    ull* op1 = (ull*)(g_att + (b * PP + p1) * EE + h * DD);
#pragma unroll
    for (int i = 0; i < 16; i++) {
        op0[i] = mul2(acc2[0][i], inv0);
        op1[i] = mul2(acc2[1][i], inv1);
    }
}

// ---------------------------------------------------------------------------
// Pointer GEMM per batch: S[p,n] = mh[b,p,:] . shk[b,:,n]
// Tile 128(p) x 64(n), K-chunk 16, f32x2 over K, double-buffered smem.
// Epilogue: exp(10*tanh(S/sqrt(E)) + mask) -> g_s2
// ---------------------------------------------------------------------------
__global__ void __launch_bounds__(256) pointer_kernel(
    const float* __restrict__ shk,
    const float* __restrict__ mask)
{
    const int b  = blockIdx.z;
    const int m0 = blockIdx.y * 128;  // p tile (2 per batch)
    const int n0 = blockIdx.x * 64;   // n tile

    const float* A  = g_mh + (long)b * PP * EE;   // [256,512] row-major
    const float* Bm = shk  + (long)b * EE * NN;   // [512,1024], B[k][n]

    __shared__ float As[2][128 * LDA];   // [p][k]
    __shared__ float Bs[2][64 * LDA];    // [n][k] (transposed on store)

    const int tx = threadIdx.x, ty = threadIdx.y;
    const int t  = ty * 16 + tx;
    const int ar = t >> 2;            // 0..63
    const int ac = (t & 3) * 4;
    const int bk = t >> 4;            // 0..15 (k row of shk)
    const int bn = (t & 15) * 4;      // 0..60 (n col)

    const float* pA0 = A + (m0 + ar) * EE + ac;
    const float* pA1 = A + (m0 + 64 + ar) * EE + ac;
    const float* pB  = Bm + bk * NN + n0 + bn;

    ull acc2[8][4];
#pragma unroll
    for (int i = 0; i < 8; i++)
#pragma unroll
        for (int j = 0; j < 4; j++) acc2[i][j] = 0ull;

    // prologue
    float4 a0 = *(const float4*)(pA0);
    float4 a1 = *(const float4*)(pA1);
    float4 bv = *(const float4*)(pB);
    *(float4*)(&As[0][ar * LDA + ac])        = a0;
    *(float4*)(&As[0][(64 + ar) * LDA + ac]) = a1;
    Bs[0][(bn + 0) * LDA + bk] = bv.x;
    Bs[0][(bn + 1) * LDA + bk] = bv.y;
    Bs[0][(bn + 2) * LDA + bk] = bv.z;
    Bs[0][(bn + 3) * LDA + bk] = bv.w;
    __syncthreads();

#pragma unroll 1
    for (int c = 0; c < 32; c++) {
        const int cur = c & 1;
        if (c < 31) {
            const int k1 = (c + 1) * 16;
            a0 = *(const float4*)(pA0 + k1);
            a1 = *(const float4*)(pA1 + k1);
            bv = *(const float4*)(pB + (long)k1 * NN);
        }
#pragma unroll
        for (int kp = 0; kp < 8; kp++) {
            ull a2[8], b2[4];
#pragma unroll
            for (int i = 0; i < 8; i++)
                a2[i] = *(const ull*)(&As[cur][(ty * 8 + i) * LDA + 2 * kp]);
#pragma unroll
            for (int j = 0; j < 4; j++)
                b2[j] = *(const ull*)(&Bs[cur][(tx * 4 + j) * LDA + 2 * kp]);
#pragma unroll
            for (int i = 0; i < 8; i++)
#pragma unroll
                for (int j = 0; j < 4; j++)
                    acc2[i][j] = fma2(a2[i], b2[j], acc2[i][j]);
        }
        if (c < 31) {
            const int nxt = cur ^ 1;
            *(float4*)(&As[nxt][ar * LDA + ac])        = a0;
            *(float4*)(&As[nxt][(64 + ar) * LDA + ac]) = a1;
            Bs[nxt][(bn + 0) * LDA + bk] = bv.x;
            Bs[nxt][(bn + 1) * LDA + bk] = bv.y;
            Bs[nxt][(bn + 2) * LDA + bk] = bv.z;
            Bs[nxt][(bn + 3) * LDA + bk] = bv.w;
            __syncthreads();
        }
    }

    const float inv_sqrt_e = 0.044194173824159216f;  // 1/sqrt(512)
#pragma unroll
    for (int i = 0; i < 8; i++) {
        const int p = m0 + ty * 8 + i;
#pragma unroll
        for (int j = 0; j < 4; j++) {
            const int n = n0 + tx * 4 + j;
            const float sc = 10.f * tanhf(hadd2(acc2[i][j]) * inv_sqrt_e);
            const long idx = ((long)b * PP + p) * NN + n;
            g_s2[idx] = __expf(sc + mask[idx]);
        }
    }
}

// ---------------------------------------------------------------------------
// Row-wise normalize g_s2 -> out
// ---------------------------------------------------------------------------
__global__ void __launch_bounds__(256) rownorm_kernel(float* __restrict__ out)
{
    const int row = blockIdx.x;           // 0..8191
    const int t = threadIdx.x;            // 0..255
    const float4* e4 = (const float4*)(g_s2 + (long)row * NN);
    float4 v = e4[t];
    float s = v.x + v.y + v.z + v.w;
#pragma unroll
    for (int o = 16; o > 0; o >>= 1) s += __shfl_xor_sync(0xffffffffu, s, o);

    __shared__ float ws[8];
    if ((t & 31) == 0) ws[t >> 5] = s;
    __syncthreads();
    if (t < 32) {
        float x = (t < 8) ? ws[t] : 0.f;
#pragma unroll
        for (int o = 4; o > 0; o >>= 1) x += __shfl_xor_sync(0xffffffffu, x, o);
        if (t == 0) ws[0] = x;
    }
    __syncthreads();
    const float inv = 1.f / ws[0];
    float4* o4 = (float4*)(out + (long)row * NN);
    o4[t] = make_float4(v.x * inv, v.y * inv, v.z * inv, v.w * inv);
}

// ---------------------------------------------------------------------------
extern "C" void kernel_launch(void* const* d_in, const int* in_sizes, int n_in,
                              void* d_out, int out_size)
{
    const float* enc   = (const float*)d_in[0];  // [B,P,E]
    const float* mask  = (const float*)d_in[1];  // [B,P,N]
    const float* qf    = (const float*)d_in[2];  // [B,H,P,D]
    const float* kmat  = (const float*)d_in[3];  // [B,H,N,D]
    const float* vmat  = (const float*)d_in[4];  // [B,H,N,D]
    const float* shk   = (const float*)d_in[5];  // [B,E,N]
    const float* wq    = (const float*)d_in[6];  // [E,E]
    const float* wc    = (const float*)d_in[7];  // [E,E]
    float* out = (float*)d_out;

    (void)in_sizes; (void)n_in; (void)out_size;

    dim3 thr(16, 16);

    // 1) q = enc @ Wq^T + q_first   (M = 8192, N = 512)
    gemm_aw_kernel<0><<<dim3(EE / 64, (BB * PP) / 128), thr>>>(enc, wq, qf);

    // 2) masked multi-head attention
    attn_kernel<<<BB * HH, 128>>>(kmat, vmat, mask);

    // 3) combine heads: mh = att @ Wc^T
    gemm_aw_kernel<1><<<dim3(EE / 64, (BB * PP) / 128), thr>>>(nullptr, wc, nullptr);

    // 4) pointer logits + clip + mask + exp
    pointer_kernel<<<dim3(NN / 64, PP / 128, BB), thr>>>(shk, mask);

    // 5) normalize rows -> probs
    rownorm_kernel<<<BB * PP, 256>>>(out);
}

// round 7
// speedup vs baseline: 1.2102x; 1.2102x over previous
#include <cuda_runtime.h>

// Problem shapes (fixed)
#define BB 32
#define PP 256
#define NN 1024
#define EE 512
#define HH 16
#define DD 32

typedef unsigned long long ull;

// Scratch (device globals: allocation-free per harness rules)
__device__ float g_q  [BB*PP*EE];   // q = q_first + enc@Wq^T, layout [B,P,(h,d)]
__device__ float g_att[BB*PP*EE];   // attention out, layout [B,P,(h,d)]
__device__ float g_mh [BB*PP*EE];   // combined heads [B,P,E]
__device__ float g_s2 [BB*PP*NN];   // exp(pointer logits) [B,P,N]

// ---- packed f32x2 helpers (sm_103a FFMA2 path) -----------------------------
__device__ __forceinline__ ull fma2(ull a, ull b, ull c) {
    ull d;
    asm("fma.rn.f32x2 %0, %1, %2, %3;" : "=l"(d) : "l"(a), "l"(b), "l"(c));
    return d;
}
__device__ __forceinline__ ull mul2(ull a, ull b) {
    ull d;
    asm("mul.rn.f32x2 %0, %1, %2;" : "=l"(d) : "l"(a), "l"(b));
    return d;
}
__device__ __forceinline__ ull pk2(float lo, float hi) {
    ull r;
    asm("mov.b64 %0, {%1, %2};" : "=l"(r) : "f"(lo), "f"(hi));
    return r;
}
__device__ __forceinline__ float hadd2(ull v) {
    float lo, hi;
    asm("mov.b64 {%0, %1}, %2;" : "=f"(lo), "=f"(hi) : "l"(v));
    return lo + hi;
}

// fast tanh: 1 - 2/(e^{2x}+1), graceful at +/-inf
__device__ __forceinline__ float fast_tanh(float x) {
    const float ex = __expf(2.f * x);
    return 1.f - __fdividef(2.f, ex + 1.f);
}

// A smem row stride 20 (16B aligned rows+fragments; half-warp broadcast reads)
// B smem row stride 18 (18*tx mod 32 hits all 16 even residues -> conflict-free)
#define LDA 20
#define LDB 18

// ---------------------------------------------------------------------------
// GEMM C[M,512] = A[M,512] @ W[512,512]^T   (C[m,n] = sum_k A[m,k] W[n,k])
// MODE 0: A=enc, epilogue adds q_first ([B,H,P,D]) -> g_q
// MODE 1: A=g_att -> g_mh
// Tile 128(m) x 64(n), K-chunk 16, 256 threads, micro 8x4 (n = tx + 16j).
// f32x2 over K; A fragments via LDS.128 (4 k at a time); double-buffered.
// ---------------------------------------------------------------------------
template <int MODE>
__global__ void __launch_bounds__(256, 2) gemm_aw_kernel(
    const float* __restrict__ Ain,
    const float* __restrict__ W,
    const float* __restrict__ qfirst)
{
    const float* A = (MODE == 0) ? Ain : g_att;
    float*       C = (MODE == 0) ? g_q : g_mh;

    __shared__ float As[2][128 * LDA];   // [m][k], k contiguous
    __shared__ float Ws[2][64 * LDB];    // [n][k], stride 18

    const int tx = threadIdx.x;       // 0..15 -> n (stride-16 groups)
    const int ty = threadIdx.y;       // 0..15 -> m
    const int t  = ty * 16 + tx;
    const int m0 = blockIdx.y * 128;
    const int n0 = blockIdx.x * 64;

    const int ar = t >> 2;            // 0..63 (row; two passes for A)
    const int ac = (t & 3) * 4;       // k col 0,4,8,12

    const float* pA0 = A + (m0 + ar) * EE + ac;
    const float* pA1 = A + (m0 + 64 + ar) * EE + ac;
    const float* pW  = W + (n0 + ar) * EE + ac;

    ull acc2[8][4];
#pragma unroll
    for (int i = 0; i < 8; i++)
#pragma unroll
        for (int j = 0; j < 4; j++) acc2[i][j] = 0ull;

    // prologue: chunk 0 -> buffer 0
    float4 a0 = *(const float4*)(pA0);
    float4 a1 = *(const float4*)(pA1);
    float4 wv = *(const float4*)(pW);
    *(float4*)(&As[0][ar * LDA + ac])        = a0;
    *(float4*)(&As[0][(64 + ar) * LDA + ac]) = a1;
    *(float2*)(&Ws[0][ar * LDB + ac])     = make_float2(wv.x, wv.y);
    *(float2*)(&Ws[0][ar * LDB + ac + 2]) = make_float2(wv.z, wv.w);
    __syncthreads();

#pragma unroll 1
    for (int c = 0; c < 32; c++) {
        const int cur = c & 1;
        if (c < 31) {
            const int k1 = (c + 1) * 16;
            a0 = *(const float4*)(pA0 + k1);
            a1 = *(const float4*)(pA1 + k1);
            wv = *(const float4*)(pW + k1);
        }
#pragma unroll
        for (int kpp = 0; kpp < 4; kpp++) {          // 4 k-values per pass
            ull b2[8];
#pragma unroll
            for (int j = 0; j < 4; j++) {
                b2[2 * j]     = *(const ull*)(&Ws[cur][(tx + 16 * j) * LDB + 4 * kpp]);
                b2[2 * j + 1] = *(const ull*)(&Ws[cur][(tx + 16 * j) * LDB + 4 * kpp + 2]);
            }
#pragma unroll
            for (int i = 0; i < 8; i++) {
                const float4 af = *(const float4*)(&As[cur][(ty * 8 + i) * LDA + 4 * kpp]);
                const ull alo = pk2(af.x, af.y);
                const ull ahi = pk2(af.z, af.w);
#pragma unroll
                for (int j = 0; j < 4; j++) {
                    acc2[i][j] = fma2(alo, b2[2 * j],     acc2[i][j]);
                    acc2[i][j] = fma2(ahi, b2[2 * j + 1], acc2[i][j]);
                }
            }
        }
        if (c < 31) {
            const int nxt = cur ^ 1;
            *(float4*)(&As[nxt][ar * LDA + ac])        = a0;
            *(float4*)(&As[nxt][(64 + ar) * LDA + ac]) = a1;
            *(float2*)(&Ws[nxt][ar * LDB + ac])     = make_float2(wv.x, wv.y);
            *(float2*)(&Ws[nxt][ar * LDB + ac + 2]) = make_float2(wv.z, wv.w);
            __syncthreads();
        }
    }

#pragma unroll
    for (int i = 0; i < 8; i++) {
        const int m = m0 + ty * 8 + i;        // m = b*256 + p
#pragma unroll
        for (int j = 0; j < 4; j++) {
            const int n = n0 + tx + 16 * j;   // n = h*32 + d
            float val = hadd2(acc2[i][j]);
            if (MODE == 0) {
                const int b = m >> 8, p = m & 255;
                const int h = n >> 5, d = n & 31;
                val += qfirst[((b * HH + h) * PP + p) * DD + d];
            }
            C[m * EE + n] = val;
        }
    }
}

// ---------------------------------------------------------------------------
// Masked attention per (b,h). 128 threads; thread owns queries p and p+128.
// f32x2 over D; 4 QK chains; k/v rows read as broadcast float4 (LDS.128).
// One-pass exp softmax (scores bounded; masked -> exact 0).
// ---------------------------------------------------------------------------
__global__ void __launch_bounds__(128) attn_kernel(
    const float* __restrict__ kmat,
    const float* __restrict__ vmat,
    const float* __restrict__ mask)
{
    const int bh = blockIdx.x;
    const int b = bh >> 4, h = bh & 15;
    const int t = threadIdx.x;        // 0..127
    const int p0 = t, p1 = t + 128;

    __shared__ float ks[128 * 32];
    __shared__ float vs[128 * 32];

    ull q2[2][16];
    {
        const ull* qp0 = (const ull*)(g_q + (b * PP + p0) * EE + h * DD);
        const ull* qp1 = (const ull*)(g_q + (b * PP + p1) * EE + h * DD);
#pragma unroll
        for (int i = 0; i < 16; i++) { q2[0][i] = qp0[i]; q2[1][i] = qp1[i]; }
    }

    ull acc2[2][16];
#pragma unroll
    for (int q = 0; q < 2; q++)
#pragma unroll
        for (int i = 0; i < 16; i++) acc2[q][i] = 0ull;
    float l0 = 0.f, l1 = 0.f;

    const float* mrow0 = mask + (b * PP + p0) * NN;
    const float* mrow1 = mask + (b * PP + p1) * NN;
    const float scale = 0.17677669529663687f;  // 1/sqrt(32)

    for (int n0 = 0; n0 < NN; n0 += 128) {
        const long base = ((long)(b * HH + h) * NN + n0) * DD;
        const float4* kg = (const float4*)(kmat + base);
        const float4* vg = (const float4*)(vmat + base);
        __syncthreads();
#pragma unroll
        for (int i = 0; i < 8; i++) {
            const int idx = i * 128 + t;    // 1024 float4 per tile
            ((float4*)ks)[idx] = kg[idx];
            ((float4*)vs)[idx] = vg[idx];
        }
        __syncthreads();

#pragma unroll 2
        for (int n = 0; n < 128; n++) {
            const float4* kr4 = (const float4*)(ks + n * 32);   // broadcast
            ull s0a = 0ull, s0b = 0ull, s1a = 0ull, s1b = 0ull;
#pragma unroll
            for (int i = 0; i < 8; i++) {
                const float4 kv4 = kr4[i];
                const ull kv0 = pk2(kv4.x, kv4.y);
                const ull kv1 = pk2(kv4.z, kv4.w);
                s0a = fma2(q2[0][2 * i],     kv0, s0a);
                s0b = fma2(q2[0][2 * i + 1], kv1, s0b);
                s1a = fma2(q2[1][2 * i],     kv0, s1a);
                s1b = fma2(q2[1][2 * i + 1], kv1, s1b);
            }
            const float e0 = __expf((hadd2(s0a) + hadd2(s0b)) * scale + mrow0[n0 + n]);
            const float e1 = __expf((hadd2(s1a) + hadd2(s1b)) * scale + mrow1[n0 + n]);
            l0 += e0; l1 += e1;
            const ull e0d = pk2(e0, e0);
            const ull e1d = pk2(e1, e1);
            const float4* vr4 = (const float4*)(vs + n * 32);
#pragma unroll
            for (int i = 0; i < 8; i++) {
                const float4 vv4 = vr4[i];
                const ull vv0 = pk2(vv4.x, vv4.y);
                const ull vv1 = pk2(vv4.z, vv4.w);
                acc2[0][2 * i]     = fma2(e0d, vv0, acc2[0][2 * i]);
                acc2[0][2 * i + 1] = fma2(e0d, vv1, acc2[0][2 * i + 1]);
                acc2[1][2 * i]     = fma2(e1d, vv0, acc2[1][2 * i]);
                acc2[1][2 * i + 1] = fma2(e1d, vv1, acc2[1][2 * i + 1]);
            }
        }
    }

    const ull inv0 = pk2(1.f / l0, 1.f / l0);
    const ull inv1 = pk2(1.f / l1, 1.f / l1);
    ull* op0 = (ull*)(g_att + (b * PP + p0) * EE + h * DD);
    ull* op1 = (ull*)(g_att + (b * PP + p1) * EE + h * DD);
#pragma unroll
    for (int i = 0; i < 16; i++) {
        op0[i] = mul2(acc2[0][i], inv0);
        op1[i] = mul2(acc2[1][i], inv1);
    }
}

// ---------------------------------------------------------------------------
// Pointer GEMM per batch: S[p,n] = mh[b,p,:] . shk[b,:,n]
// Tile 128(p) x 64(n), K-chunk 16, f32x2 over K, A frags via LDS.128,
// conflict-free B reads (stride-18, n = tx + 16j), double-buffered.
// Epilogue: exp(10*tanh(S/sqrt(E)) + mask) -> g_s2
// ---------------------------------------------------------------------------
__global__ void __launch_bounds__(256, 2) pointer_kernel(
    const float* __restrict__ shk,
    const float* __restrict__ mask)
{
    const int b  = blockIdx.z;
    const int m0 = blockIdx.y * 128;  // p tile (2 per batch)
    const int n0 = blockIdx.x * 64;   // n tile

    const float* A  = g_mh + (long)b * PP * EE;   // [256,512] row-major
    const float* Bm = shk  + (long)b * EE * NN;   // [512,1024], B[k][n]

    __shared__ float As[2][128 * LDA];   // [p][k]
    __shared__ float Bs[2][64 * LDB];    // [n][k] (transposed on store)

    const int tx = threadIdx.x, ty = threadIdx.y;
    const int t  = ty * 16 + tx;
    const int ar = t >> 2;            // 0..63
    const int ac = (t & 3) * 4;
    const int bk = t >> 4;            // 0..15 (k row of shk)
    const int bn = (t & 15) * 4;      // 0..60 (n col)

    const float* pA0 = A + (m0 + ar) * EE + ac;
    const float* pA1 = A + (m0 + 64 + ar) * EE + ac;
    const float* pB  = Bm + bk * NN + n0 + bn;

    ull acc2[8][4];
#pragma unroll
    for (int i = 0; i < 8; i++)
#pragma unroll
        for (int j = 0; j < 4; j++) acc2[i][j] = 0ull;

    // prologue
    float4 a0 = *(const float4*)(pA0);
    float4 a1 = *(const float4*)(pA1);
    float4 bv = *(const float4*)(pB);
    *(float4*)(&As[0][ar * LDA + ac])        = a0;
    *(float4*)(&As[0][(64 + ar) * LDA + ac]) = a1;
    Bs[0][(bn + 0) * LDB + bk] = bv.x;
    Bs[0][(bn + 1) * LDB + bk] = bv.y;
    Bs[0][(bn + 2) * LDB + bk] = bv.z;
    Bs[0][(bn + 3) * LDB + bk] = bv.w;
    __syncthreads();

#pragma unroll 1
    for (int c = 0; c < 32; c++) {
        const int cur = c & 1;
        if (c < 31) {
            const int k1 = (c + 1) * 16;
            a0 = *(const float4*)(pA0 + k1);
            a1 = *(const float4*)(pA1 + k1);
            bv = *(const float4*)(pB + (long)k1 * NN);
        }
#pragma unroll
        for (int kpp = 0; kpp < 4; kpp++) {
            ull b2[8];
#pragma unroll
            for (int j = 0; j < 4; j++) {
                b2[2 * j]     = *(const ull*)(&Bs[cur][(tx + 16 * j) * LDB + 4 * kpp]);
                b2[2 * j + 1] = *(const ull*)(&Bs[cur][(tx + 16 * j) * LDB + 4 * kpp + 2]);
            }
#pragma unroll
            for (int i = 0; i < 8; i++) {
                const float4 af = *(const float4*)(&As[cur][(ty * 8 + i) * LDA + 4 * kpp]);
                const ull alo = pk2(af.x, af.y);
                const ull ahi = pk2(af.z, af.w);
#pragma unroll
                for (int j = 0; j < 4; j++) {
                    acc2[i][j] = fma2(alo, b2[2 * j],     acc2[i][j]);
                    acc2[i][j] = fma2(ahi, b2[2 * j + 1], acc2[i][j]);
                }
            }
        }
        if (c < 31) {
            const int nxt = cur ^ 1;
            *(float4*)(&As[nxt][ar * LDA + ac])        = a0;
            *(float4*)(&As[nxt][(64 + ar) * LDA + ac]) = a1;
            Bs[nxt][(bn + 0) * LDB + bk] = bv.x;
            Bs[nxt][(bn + 1) * LDB + bk] = bv.y;
            Bs[nxt][(bn + 2) * LDB + bk] = bv.z;
            Bs[nxt][(bn + 3) * LDB + bk] = bv.w;
            __syncthreads();
        }
    }

    const float inv_sqrt_e = 0.044194173824159216f;  // 1/sqrt(512)
#pragma unroll
    for (int i = 0; i < 8; i++) {
        const int p = m0 + ty * 8 + i;
#pragma unroll
        for (int j = 0; j < 4; j++) {
            const int n = n0 + tx + 16 * j;
            const float sc = 10.f * fast_tanh(hadd2(acc2[i][j]) * inv_sqrt_e);
            const long idx = ((long)b * PP + p) * NN + n;
            g_s2[idx] = __expf(sc + mask[idx]);
        }
    }
}

// ---------------------------------------------------------------------------
// Row-wise normalize g_s2 -> out (streaming stores: out has no reuse)
// ---------------------------------------------------------------------------
__global__ void __launch_bounds__(256) rownorm_kernel(float* __restrict__ out)
{
    const int row = blockIdx.x;           // 0..8191
    const int t = threadIdx.x;            // 0..255
    const float4* e4 = (const float4*)(g_s2 + (long)row * NN);
    float4 v = e4[t];
    float s = v.x + v.y + v.z + v.w;
#pragma unroll
    for (int o = 16; o > 0; o >>= 1) s += __shfl_xor_sync(0xffffffffu, s, o);

    __shared__ float ws[8];
    if ((t & 31) == 0) ws[t >> 5] = s;
    __syncthreads();
    if (t < 32) {
        float x = (t < 8) ? ws[t] : 0.f;
#pragma unroll
        for (int o = 4; o > 0; o >>= 1) x += __shfl_xor_sync(0xffffffffu, x, o);
        if (t == 0) ws[0] = x;
    }
    __syncthreads();
    const float inv = 1.f / ws[0];
    float4* o4 = (float4*)(out + (long)row * NN);
    const float4 r = make_float4(v.x * inv, v.y * inv, v.z * inv, v.w * inv);
    __stcs(&o4[t], r);
}

// ---------------------------------------------------------------------------
extern "C" void kernel_launch(void* const* d_in, const int* in_sizes, int n_in,
                              void* d_out, int out_size)
{
    const float* enc   = (const float*)d_in[0];  // [B,P,E]
    const float* mask  = (const float*)d_in[1];  // [B,P,N]
    const float* qf    = (const float*)d_in[2];  // [B,H,P,D]
    const float* kmat  = (const float*)d_in[3];  // [B,H,N,D]
    const float* vmat  = (const float*)d_in[4];  // [B,H,N,D]
    const float* shk   = (const float*)d_in[5];  // [B,E,N]
    const float* wq    = (const float*)d_in[6];  // [E,E]
    const float* wc    = (const float*)d_in[7];  // [E,E]
    float* out = (float*)d_out;

    (void)in_sizes; (void)n_in; (void)out_size;

    dim3 thr(16, 16);

    // 1) q = enc @ Wq^T + q_first   (M = 8192, N = 512)
    gemm_aw_kernel<0><<<dim3(EE / 64, (BB * PP) / 128), thr>>>(enc, wq, qf);

    // 2) masked multi-head attention
    attn_kernel<<<BB * HH, 128>>>(kmat, vmat, mask);

    // 3) combine heads: mh = att @ Wc^T
    gemm_aw_kernel<1><<<dim3(EE / 64, (BB * PP) / 128), thr>>>(nullptr, wc, nullptr);

    // 4) pointer logits + clip + mask + exp
    pointer_kernel<<<dim3(NN / 64, PP / 128, BB), thr>>>(shk, mask);

    // 5) normalize rows -> probs
    rownorm_kernel<<<BB * PP, 256>>>(out);
}